// round 6
// baseline (speedup 1.0000x reference)
#include <cuda_runtime.h>
#include <cstdint>

#define Bb 2
#define Ss 2048
#define Dd 1024
#define Hh 16
#define BSD (Bb * Ss * Dd) /* 4194304 */

static __device__ float g_q[BSD];
static __device__ float g_att[BSD];
static __device__ float g_k[BSD];
static __device__ float g_v[BSD];

__device__ __forceinline__ unsigned f2tf(float x) {
    unsigned r;
    asm("cvt.rna.tf32.f32 %0, %1;" : "=r"(r) : "f"(x));
    return r;
}

__device__ __forceinline__ void mma8(float* c, const unsigned* a, const unsigned* b) {
    asm volatile(
        "mma.sync.aligned.m16n8k8.row.col.f32.tf32.tf32.f32 "
        "{%0,%1,%2,%3}, {%4,%5,%6,%7}, {%8,%9}, {%0,%1,%2,%3};\n"
        : "+f"(c[0]), "+f"(c[1]), "+f"(c[2]), "+f"(c[3])
        : "r"(a[0]), "r"(a[1]), "r"(a[2]), "r"(a[3]), "r"(b[0]), "r"(b[1]));
}

__device__ __forceinline__ uint32_t smem_u32(const void* p) {
    uint32_t a;
    asm("{ .reg .u64 t; cvta.to.shared.u64 t, %1; cvt.u32.u64 %0, t; }"
        : "=r"(a) : "l"(p));
    return a;
}

#define CP_ASYNC16(dst, src) \
    asm volatile("cp.async.cg.shared.global [%0], [%1], 16;" :: "r"(dst), "l"(src))
#define CP_COMMIT() asm volatile("cp.async.commit_group;" ::: "memory")
#define CP_WAIT(n)  asm volatile("cp.async.wait_group %0;" :: "n"(n) : "memory")

// ===========================================================================
// GEMM: C = A @ W^T + bias. 128x128 tile, BK=32, 128 thr / 4 warps,
// warp tile 64x64. cp.async double-buffered raw-fp32 staging; tf32 cvt on
// fragment load. 2 CTAs/SM.
// ===========================================================================
#define GST 36
#define GBUF (128 * GST)                 /* 4608 floats per operand buffer */
#define GEMM_SMEM_BYTES (4 * GBUF * 4)   /* 73728 */

__device__ __forceinline__
void gemm_core(const float* __restrict__ A, const float* __restrict__ W,
               const float* __restrict__ bias, float* __restrict__ C,
               int N, int K, int bm, int bn, float* smf)
{
    // smf layout: A0 | A1 | B0 | B1, each GBUF floats
    const int tid = threadIdx.x;
    const int w = tid >> 5, lane = tid & 31;
    const int g = lane >> 2, t = lane & 3;
    const int wm = (w & 1) * 64;
    const int wn = (w >> 1) * 64;

    const int arow = tid >> 3;        // 0..15 (+16*l)
    const int ac4  = (tid & 7) << 2;  // 0..28
    const float* Ab = A + (size_t)(bm + arow) * K + ac4;
    const float* Wb = W + (size_t)(bn + arow) * K + ac4;
    const uint32_t sA0 = smem_u32(smf);
    const uint32_t sB0 = smem_u32(smf + 2 * GBUF);

    float c[4][8][4] = {};
    const int NCH = K / 32;

    // prologue: stream chunk 0 into buffer 0
#pragma unroll
    for (int l = 0; l < 8; l++) {
        const uint32_t off = ((arow + 16 * l) * GST + ac4) * 4;
        CP_ASYNC16(sA0 + off, Ab + (size_t)(16 * l) * K);
        CP_ASYNC16(sB0 + off, Wb + (size_t)(16 * l) * K);
    }
    CP_COMMIT();

    for (int ch = 0; ch < NCH; ch++) {
        if (ch + 1 < NCH) {
            const uint32_t bo = (uint32_t)(((ch + 1) & 1) * GBUF) * 4;
            const float* ap = Ab + (ch + 1) * 32;
            const float* wp = Wb + (ch + 1) * 32;
#pragma unroll
            for (int l = 0; l < 8; l++) {
                const uint32_t off = ((arow + 16 * l) * GST + ac4) * 4;
                CP_ASYNC16(sA0 + bo + off, ap + (size_t)(16 * l) * K);
                CP_ASYNC16(sB0 + bo + off, wp + (size_t)(16 * l) * K);
            }
            CP_COMMIT();
            CP_WAIT(1);
        } else {
            CP_WAIT(0);
        }
        __syncthreads();

        const float* AsF = smf + (ch & 1) * GBUF;
        const float* BsF = smf + 2 * GBUF + (ch & 1) * GBUF;
#pragma unroll
        for (int kk = 0; kk < 4; kk++) {
            const int k = kk * 8;
            unsigned a[4][4];
#pragma unroll
            for (int mt = 0; mt < 4; mt++) {
                const int rb = wm + mt * 16;
                a[mt][0] = f2tf(AsF[(rb + g) * GST + k + t]);
                a[mt][1] = f2tf(AsF[(rb + g + 8) * GST + k + t]);
                a[mt][2] = f2tf(AsF[(rb + g) * GST + k + t + 4]);
                a[mt][3] = f2tf(AsF[(rb + g + 8) * GST + k + t + 4]);
            }
#pragma unroll
            for (int nt = 0; nt < 8; nt++) {
                const int nb = wn + nt * 8;
                unsigned b[2];
                b[0] = f2tf(BsF[(nb + g) * GST + k + t]);
                b[1] = f2tf(BsF[(nb + g) * GST + k + t + 4]);
#pragma unroll
                for (int mt = 0; mt < 4; mt++)
                    mma8(c[mt][nt], a[mt], b);
            }
        }
        __syncthreads();
    }

#pragma unroll
    for (int mt = 0; mt < 4; mt++) {
        const int r0 = bm + wm + mt * 16 + g;
#pragma unroll
        for (int nt = 0; nt < 8; nt++) {
            const int col = bn + wn + nt * 8 + 2 * t;
            const float2 bv = *(const float2*)(bias + col);
            float2 o0 = {c[mt][nt][0] + bv.x, c[mt][nt][1] + bv.y};
            float2 o1 = {c[mt][nt][2] + bv.x, c[mt][nt][3] + bv.y};
            *(float2*)(C + (size_t)r0 * N + col) = o0;
            *(float2*)(C + (size_t)(r0 + 8) * N + col) = o1;
        }
    }
}

__global__ __launch_bounds__(128, 2)
void gemm_tf32(const float* __restrict__ A, const float* __restrict__ W,
               const float* __restrict__ bias, float* __restrict__ C,
               int N, int K)
{
    extern __shared__ float gsm[];
    gemm_core(A, W, bias, C, N, K, blockIdx.y * 128, blockIdx.x * 128, gsm);
}

// Fused Q/K/V projections: blockIdx.z selects the operand triple.
__global__ __launch_bounds__(128, 2)
void qkv_gemm(const float* A0, const float* A1, const float* A2,
              const float* W0, const float* W1, const float* W2,
              const float* b0, const float* b1, const float* b2,
              float* C0, float* C1, float* C2, int N, int K)
{
    extern __shared__ float gsm[];
    const int z = blockIdx.z;
    const float* A = (z == 0) ? A0 : (z == 1) ? A1 : A2;
    const float* W = (z == 0) ? W0 : (z == 1) ? W1 : W2;
    const float* bi = (z == 0) ? b0 : (z == 1) ? b1 : b2;
    float* C = (z == 0) ? C0 : (z == 1) ? C1 : C2;
    gemm_core(A, W, bi, C, N, K, blockIdx.y * 128, blockIdx.x * 128, gsm);
}

// ===========================================================================
// Attention: 128 thr (4 warps x 32 q-rows), 2 CTAs/SM. k-tiles of 32.
// K/V double-buffered via cp.async (raw fp32, cvt on fragment load);
// bias register-prefetched. No max-subtraction; normalize at the end.
// ===========================================================================
#define KTILE 32
#define QST 68
#define KST 68
#define VST 72
#define PST 36
#define KBUF (KTILE * KST)   /* 2176 */
#define VBUF (KTILE * VST)   /* 2304 */
#define AOFF_K 8704                       /* after Qs 128*QST */
#define AOFF_V (AOFF_K + 2 * KBUF)        /* 13056 */
#define AOFF_P (AOFF_V + 2 * VBUF)        /* 17664 */
#define ATTN_SM_UINTS (AOFF_P + 128 * PST)/* 22272 */
#define ATTN_SM_BYTES (ATTN_SM_UINTS * 4) /* 89088 */

__global__ __launch_bounds__(128, 2)
void attn_tf32(const float* __restrict__ Q, const float* __restrict__ Kc,
               const float* __restrict__ Vc, const float* __restrict__ bias,
               float* __restrict__ O)
{
    extern __shared__ unsigned sm[];
    unsigned* Qs = sm;
    float* Kf = (float*)(sm + AOFF_K);
    float* Vf = (float*)(sm + AOFF_V);
    unsigned* Ps = sm + AOFF_P;

    const int tid = threadIdx.x;
    const int w = tid >> 5, lane = tid & 31;
    const int g = lane >> 2, t = lane & 3;
    const int q0 = blockIdx.x * 128;
    const int bh = blockIdx.y;
    const int b = bh >> 4, h = bh & 15;

    // staging coords for K/V tiles (32 rows x 16 float4)
    const int sr = tid >> 4;          // 0..7 (+8*l)
    const int sc4 = (tid & 15) << 2;  // 0..60
    const float* KbBase = Kc + (size_t)b * Ss * Dd + h * 64 + sc4;
    const float* VbBase = Vc + (size_t)b * Ss * Dd + h * 64 + sc4;
    const float* biasBase = bias + (size_t)b * Ss * Ss + (size_t)(q0 + w * 32 + g) * Ss;
    const uint32_t sKf = smem_u32(Kf);
    const uint32_t sVf = smem_u32(Vf);

    // prologue: stream KV tile 0 into buffer 0
#pragma unroll
    for (int l = 0; l < 4; l++) {
        CP_ASYNC16(sKf + ((sr + 8 * l) * KST + sc4) * 4,
                   KbBase + (size_t)(sr + 8 * l) * Dd);
        CP_ASYNC16(sVf + ((sr + 8 * l) * VST + sc4) * 4,
                   VbBase + (size_t)(sr + 8 * l) * Dd);
    }
    CP_COMMIT();

    // bias tile 0 prefetch (registers)
    float2 pbias[2][4][2];
#pragma unroll
    for (int mt = 0; mt < 2; mt++)
#pragma unroll
        for (int nt = 0; nt < 4; nt++)
#pragma unroll
            for (int rr = 0; rr < 2; rr++)
                pbias[mt][nt][rr] =
                    *(const float2*)(biasBase + (size_t)(mt * 16 + rr * 8) * Ss + nt * 8 + 2 * t);

    // stage Q (scaled by 1/8, tf32)
    const float* Qb = Q + ((size_t)b * Ss + q0) * Dd + h * 64;
#pragma unroll
    for (int l = 0; l < 16; l++) {
        int idx = tid + l * 128;
        int r = idx >> 4;
        int c4 = (idx & 15) << 2;
        float4 v = *(const float4*)(Qb + (size_t)r * Dd + c4);
        uint4 u = {f2tf(v.x * 0.125f), f2tf(v.y * 0.125f),
                   f2tf(v.z * 0.125f), f2tf(v.w * 0.125f)};
        *(uint4*)&Qs[r * QST + c4] = u;
    }

    float o[2][8][4] = {};
    float lr[2][2] = {};
    unsigned* Pw = Ps + (w * 32) * PST;
    const unsigned* Qw = Qs + (w * 32) * QST;

    const int NIT = Ss / KTILE;   // 64
    for (int it = 0; it < NIT; it++) {
        if (it + 1 < NIT) {
            const uint32_t kbo = (uint32_t)(((it + 1) & 1) * KBUF) * 4;
            const uint32_t vbo = (uint32_t)(((it + 1) & 1) * VBUF) * 4;
            const float* kp = KbBase + (size_t)(it + 1) * KTILE * Dd;
            const float* vp = VbBase + (size_t)(it + 1) * KTILE * Dd;
#pragma unroll
            for (int l = 0; l < 4; l++) {
                CP_ASYNC16(sKf + kbo + ((sr + 8 * l) * KST + sc4) * 4,
                           kp + (size_t)(sr + 8 * l) * Dd);
                CP_ASYNC16(sVf + vbo + ((sr + 8 * l) * VST + sc4) * 4,
                           vp + (size_t)(sr + 8 * l) * Dd);
            }
            CP_COMMIT();
            CP_WAIT(1);
        } else {
            CP_WAIT(0);
        }
        __syncthreads();

        const float* Kcur = Kf + (it & 1) * KBUF;
        const float* Vcur = Vf + (it & 1) * VBUF;

        // S = (Q/8) @ K^T : warp tile 32 x 32
        float s[2][4][4] = {};
#pragma unroll
        for (int kk = 0; kk < 8; kk++) {
            const int k = kk * 8;
            unsigned a[2][4];
#pragma unroll
            for (int mt = 0; mt < 2; mt++) {
                const int rb = mt * 16;
                a[mt][0] = Qw[(rb + g) * QST + k + t];
                a[mt][1] = Qw[(rb + g + 8) * QST + k + t];
                a[mt][2] = Qw[(rb + g) * QST + k + t + 4];
                a[mt][3] = Qw[(rb + g + 8) * QST + k + t + 4];
            }
#pragma unroll
            for (int nt = 0; nt < 4; nt++) {
                unsigned bb[2];
                bb[0] = f2tf(Kcur[(nt * 8 + g) * KST + k + t]);
                bb[1] = f2tf(Kcur[(nt * 8 + g) * KST + k + t + 4]);
                mma8(s[0][nt], a[0], bb);
                mma8(s[1][nt], a[1], bb);
            }
        }

        // + bias, exp, row-sums, store P (tf32)
#pragma unroll
        for (int mt = 0; mt < 2; mt++)
#pragma unroll
            for (int nt = 0; nt < 4; nt++) {
                const float2 b0 = pbias[mt][nt][0];
                const float2 b1 = pbias[mt][nt][1];
                float p0 = __expf(s[mt][nt][0] + b0.x);
                float p1 = __expf(s[mt][nt][1] + b0.y);
                float p2 = __expf(s[mt][nt][2] + b1.x);
                float p3 = __expf(s[mt][nt][3] + b1.y);
                lr[mt][0] += p0 + p1;
                lr[mt][1] += p2 + p3;
                uint2 u0 = {f2tf(p0), f2tf(p1)};
                uint2 u1 = {f2tf(p2), f2tf(p3)};
                *(uint2*)&Pw[(mt * 16 + g) * PST + nt * 8 + 2 * t] = u0;
                *(uint2*)&Pw[(mt * 16 + g + 8) * PST + nt * 8 + 2 * t] = u1;
            }

        // prefetch next bias tile (consumed next iteration)
        if (it + 1 < NIT) {
            const float* bp = biasBase + (it + 1) * KTILE;
#pragma unroll
            for (int mt = 0; mt < 2; mt++)
#pragma unroll
                for (int nt = 0; nt < 4; nt++)
#pragma unroll
                    for (int rr = 0; rr < 2; rr++)
                        pbias[mt][nt][rr] =
                            *(const float2*)(bp + (size_t)(mt * 16 + rr * 8) * Ss + nt * 8 + 2 * t);
        }
        __syncwarp();

        // O += P @ V : warp tile 32 x 64, depth 32
#pragma unroll
        for (int kk = 0; kk < 4; kk++) {
            const int k = kk * 8;
            unsigned a[2][4];
#pragma unroll
            for (int mt = 0; mt < 2; mt++) {
                const int rb = mt * 16;
                a[mt][0] = Pw[(rb + g) * PST + k + t];
                a[mt][1] = Pw[(rb + g + 8) * PST + k + t];
                a[mt][2] = Pw[(rb + g) * PST + k + t + 4];
                a[mt][3] = Pw[(rb + g + 8) * PST + k + t + 4];
            }
#pragma unroll
            for (int nt = 0; nt < 8; nt++) {
                unsigned bb[2];
                bb[0] = f2tf(Vcur[(k + t) * VST + nt * 8 + g]);
                bb[1] = f2tf(Vcur[(k + t + 4) * VST + nt * 8 + g]);
                mma8(o[0][nt], a[0], bb);
                mma8(o[1][nt], a[1], bb);
            }
        }
        __syncthreads();
    }

#pragma unroll
    for (int mt = 0; mt < 2; mt++)
#pragma unroll
        for (int hf = 0; hf < 2; hf++) {
            float v = lr[mt][hf];
            v += __shfl_xor_sync(0xffffffffu, v, 1);
            v += __shfl_xor_sync(0xffffffffu, v, 2);
            lr[mt][hf] = 1.f / v;
        }

    float* Ob = O + ((size_t)b * Ss + q0 + w * 32) * Dd + h * 64;
#pragma unroll
    for (int mt = 0; mt < 2; mt++)
#pragma unroll
        for (int nt = 0; nt < 8; nt++) {
            const int cg = nt * 8 + 2 * t;
            float2 r0v = {o[mt][nt][0] * lr[mt][0], o[mt][nt][1] * lr[mt][0]};
            float2 r1v = {o[mt][nt][2] * lr[mt][1], o[mt][nt][3] * lr[mt][1]};
            *(float2*)(Ob + (size_t)(mt * 16 + g) * Dd + cg) = r0v;
            *(float2*)(Ob + (size_t)(mt * 16 + g + 8) * Dd + cg) = r1v;
        }
}

// ---------------------------------------------------------------------------
extern "C" void kernel_launch(void* const* d_in, const int* in_sizes, int n_in,
                              void* d_out, int out_size)
{
    (void)in_sizes; (void)n_in;
    const float* queries   = (const float*)d_in[0];
    const float* keys      = (const float*)d_in[1];
    const float* values    = (const float*)d_in[2];
    const float* attn_bias = (const float*)d_in[3];
    const float* Wq = (const float*)d_in[4];
    const float* bq = (const float*)d_in[5];
    const float* Wk = (const float*)d_in[6];
    const float* bk = (const float*)d_in[7];
    const float* Wv = (const float*)d_in[8];
    const float* bv = (const float*)d_in[9];
    const float* Wo = (const float*)d_in[10];
    const float* bo = (const float*)d_in[11];

    float* out = (float*)d_out;

    float *pq, *patt, *pk, *pv;
    cudaGetSymbolAddress((void**)&pq,   g_q);
    cudaGetSymbolAddress((void**)&patt, g_att);
    cudaGetSymbolAddress((void**)&pk,   g_k);
    cudaGetSymbolAddress((void**)&pv,   g_v);

    const bool full_out = (out_size >= 3 * BSD);
    float* kdst = full_out ? out + BSD     : pk;
    float* vdst = full_out ? out + 2 * BSD : pv;

    cudaFuncSetAttribute(attn_tf32, cudaFuncAttributeMaxDynamicSharedMemorySize,
                         ATTN_SM_BYTES);
    cudaFuncSetAttribute(qkv_gemm, cudaFuncAttributeMaxDynamicSharedMemorySize,
                         GEMM_SMEM_BYTES);
    cudaFuncSetAttribute(gemm_tf32, cudaFuncAttributeMaxDynamicSharedMemorySize,
                         GEMM_SMEM_BYTES);

    dim3 qkvgrid(Dd / 128, (Bb * Ss) / 128, 3);  // (8, 32, 3)
    qkv_gemm<<<qkvgrid, 128, GEMM_SMEM_BYTES>>>(queries, keys, values,
                                                Wq, Wk, Wv, bq, bk, bv,
                                                pq, kdst, vdst, Dd, Dd);

    dim3 agrid(Ss / 128, Bb * Hh);               // (16, 32)
    attn_tf32<<<agrid, 128, ATTN_SM_BYTES>>>(pq, kdst, vdst, attn_bias, patt);

    dim3 ggrid(Dd / 128, (Bb * Ss) / 128);       // (8, 32)
    gemm_tf32<<<ggrid, 128, GEMM_SMEM_BYTES>>>(patt, Wo, bo, out, Dd, Dd);
}

// round 7
// speedup vs baseline: 1.4130x; 1.4130x over previous
#include <cuda_runtime.h>
#include <cuda_fp16.h>
#include <cstdint>

#define Bb 2
#define Ss 2048
#define Dd 1024
#define Hh 16
#define BSD (Bb * Ss * Dd) /* 4194304 */

static __device__ float g_q[BSD];
static __device__ float g_att[BSD];
static __device__ float g_k[BSD];
static __device__ float g_v[BSD];

// lo goes to low 16 bits (lower k index), hi to high bits
__device__ __forceinline__ unsigned f2h2(float lo, float hi) {
    __half2 h = __floats2half2_rn(lo, hi);
    return *(unsigned*)&h;
}

__device__ __forceinline__ void mma16(float* c, const unsigned* a, const unsigned* b) {
    asm volatile(
        "mma.sync.aligned.m16n8k16.row.col.f32.f16.f16.f32 "
        "{%0,%1,%2,%3}, {%4,%5,%6,%7}, {%8,%9}, {%0,%1,%2,%3};\n"
        : "+f"(c[0]), "+f"(c[1]), "+f"(c[2]), "+f"(c[3])
        : "r"(a[0]), "r"(a[1]), "r"(a[2]), "r"(a[3]), "r"(b[0]), "r"(b[1]));
}

// ===========================================================================
// GEMM: C = A @ W^T + bias (fp16 mma, fp32 accum). 128x128 tile, BK=32,
// 256 thr / 8 warps, warp tile 32x64. Register-prefetch pipeline. 2 CTAs/SM.
// Smem: [row][kpair] u32, stride 20 -> fragment bank = (20g+t) mod 32, CF.
// ===========================================================================
#define GST2 20

__device__ __forceinline__
void gemm_core(const float* __restrict__ A, const float* __restrict__ W,
               const float* __restrict__ bias, float* __restrict__ C,
               int N, int K, int bm, int bn, unsigned* As, unsigned* Bs)
{
    const int tid = threadIdx.x;
    const int w = tid >> 5, lane = tid & 31;
    const int g = lane >> 2, t = lane & 3;
    const int wm = (w & 3) * 32;
    const int wn = (w >> 2) * 64;

    const int arow = tid >> 3;        // 0..31 (+32*l)
    const int ac4  = (tid & 7) << 2;  // float col 0..28
    const int akp  = ac4 >> 1;        // kpair col 0..14 (even)
    const float* Ab = A + (size_t)(bm + arow) * K + ac4;
    const float* Wb = W + (size_t)(bn + arow) * K + ac4;

    float c[2][8][4] = {};
    float4 pa[4], pb[4];

#pragma unroll
    for (int l = 0; l < 4; l++) {
        pa[l] = *(const float4*)(Ab + (size_t)(32 * l) * K);
        pb[l] = *(const float4*)(Wb + (size_t)(32 * l) * K);
    }

    const int NCH = K / 32;
    for (int ch = 0; ch < NCH; ch++) {
#pragma unroll
        for (int l = 0; l < 4; l++) {
            const int r = arow + 32 * l;
            As[r * GST2 + akp]     = f2h2(pa[l].x, pa[l].y);
            As[r * GST2 + akp + 1] = f2h2(pa[l].z, pa[l].w);
            Bs[r * GST2 + akp]     = f2h2(pb[l].x, pb[l].y);
            Bs[r * GST2 + akp + 1] = f2h2(pb[l].z, pb[l].w);
        }
        __syncthreads();

        if (ch + 1 < NCH) {
            const float* ap = Ab + (ch + 1) * 32;
            const float* wp = Wb + (ch + 1) * 32;
#pragma unroll
            for (int l = 0; l < 4; l++) {
                pa[l] = *(const float4*)(ap + (size_t)(32 * l) * K);
                pb[l] = *(const float4*)(wp + (size_t)(32 * l) * K);
            }
        }

#pragma unroll
        for (int kk = 0; kk < 2; kk++) {
            const int kb = kk * 8;
            unsigned a[2][4];
#pragma unroll
            for (int mt = 0; mt < 2; mt++) {
                const int rb = wm + mt * 16;
                a[mt][0] = As[(rb + g) * GST2 + kb + t];
                a[mt][1] = As[(rb + g + 8) * GST2 + kb + t];
                a[mt][2] = As[(rb + g) * GST2 + kb + t + 4];
                a[mt][3] = As[(rb + g + 8) * GST2 + kb + t + 4];
            }
#pragma unroll
            for (int nt = 0; nt < 8; nt++) {
                const int nb = wn + nt * 8;
                unsigned b[2];
                b[0] = Bs[(nb + g) * GST2 + kb + t];
                b[1] = Bs[(nb + g) * GST2 + kb + t + 4];
                mma16(c[0][nt], a[0], b);
                mma16(c[1][nt], a[1], b);
            }
        }
        __syncthreads();
    }

#pragma unroll
    for (int mt = 0; mt < 2; mt++) {
        const int r0 = bm + wm + mt * 16 + g;
#pragma unroll
        for (int nt = 0; nt < 8; nt++) {
            const int col = bn + wn + nt * 8 + 2 * t;
            const float2 bv = *(const float2*)(bias + col);
            float2 o0 = {c[mt][nt][0] + bv.x, c[mt][nt][1] + bv.y};
            float2 o1 = {c[mt][nt][2] + bv.x, c[mt][nt][3] + bv.y};
            *(float2*)(C + (size_t)r0 * N + col) = o0;
            *(float2*)(C + (size_t)(r0 + 8) * N + col) = o1;
        }
    }
}

__global__ __launch_bounds__(256, 2)
void gemm_f16(const float* __restrict__ A, const float* __restrict__ W,
              const float* __restrict__ bias, float* __restrict__ C,
              int N, int K)
{
    __shared__ unsigned As[128 * GST2];
    __shared__ unsigned Bs[128 * GST2];
    gemm_core(A, W, bias, C, N, K, blockIdx.y * 128, blockIdx.x * 128, As, Bs);
}

__global__ __launch_bounds__(256, 2)
void qkv_gemm(const float* A0, const float* A1, const float* A2,
              const float* W0, const float* W1, const float* W2,
              const float* b0, const float* b1, const float* b2,
              float* C0, float* C1, float* C2, int N, int K)
{
    __shared__ unsigned As[128 * GST2];
    __shared__ unsigned Bs[128 * GST2];
    const int z = blockIdx.z;
    const float* A = (z == 0) ? A0 : (z == 1) ? A1 : A2;
    const float* W = (z == 0) ? W0 : (z == 1) ? W1 : W2;
    const float* bi = (z == 0) ? b0 : (z == 1) ? b1 : b2;
    float* C = (z == 0) ? C0 : (z == 1) ? C1 : C2;
    gemm_core(A, W, bi, C, N, K, blockIdx.y * 128, blockIdx.x * 128, As, Bs);
}

// ===========================================================================
// Attention (fp16 mma): 128 thr (4 warps x 32 q-rows), 2 CTAs/SM, k-tiles 32.
// Q/K packed half2 along d ([row][36] u32); V transposed-packed along k
// ([d][17] u32); P packed half2 along k ([row][20] u32).
// exp2 folding: Q pre-scaled by 0.125*log2e; exp(s+b) = exp2(s' + b*log2e).
// No max-subtraction; normalize at the end.
// ===========================================================================
#define KTILE 32
#define QST2 36
#define KST2 36
#define VST2 17
#define PST2 20
#define AOF_K 4608                       /* Qs 128*36 */
#define AOF_V (AOF_K + KTILE * KST2)     /* 5760 */
#define AOF_P (AOF_V + 64 * VST2)        /* 6848 */
#define ATTN_UINTS (AOF_P + 128 * PST2)  /* 9408 -> 37632 B */
#define QPRE 0.18033688011112042f        /* 0.125 * log2(e) */
#define LOG2E 1.4426950408889634f

__global__ __launch_bounds__(128, 2)
void attn_f16(const float* __restrict__ Q, const float* __restrict__ Kc,
              const float* __restrict__ Vc, const float* __restrict__ bias,
              float* __restrict__ O)
{
    __shared__ unsigned sm[ATTN_UINTS];
    unsigned* Qs = sm;
    unsigned* Ks = sm + AOF_K;
    unsigned* Vt = sm + AOF_V;
    unsigned* Ps = sm + AOF_P;

    const int tid = threadIdx.x;
    const int w = tid >> 5, lane = tid & 31;
    const int g = lane >> 2, t = lane & 3;
    const int q0 = blockIdx.x * 128;
    const int bh = blockIdx.y;
    const int b = bh >> 4, h = bh & 15;

    const int sr = tid >> 4;          // 0..7
    const int sc4 = (tid & 15) << 2;  // 0..60
    const int skp = sc4 >> 1;         // 0..30 even
    const float* KbBase = Kc + (size_t)b * Ss * Dd + h * 64 + sc4;
    const float* VbBase = Vc + (size_t)b * Ss * Dd + h * 64 + sc4;
    const float* biasBase = bias + (size_t)b * Ss * Ss + (size_t)(q0 + w * 32 + g) * Ss;

    // prologue prefetch: K rows sr+8l (l=0..3); V row-pairs kp=sr+8l (l=0..1)
    float4 pk[4], pva[2], pvb[2];
#pragma unroll
    for (int l = 0; l < 4; l++)
        pk[l] = *(const float4*)(KbBase + (size_t)(sr + 8 * l) * Dd);
#pragma unroll
    for (int l = 0; l < 2; l++) {
        const int kp = sr + 8 * l;
        pva[l] = *(const float4*)(VbBase + (size_t)(2 * kp) * Dd);
        pvb[l] = *(const float4*)(VbBase + (size_t)(2 * kp + 1) * Dd);
    }
    float2 pbias[2][4][2];
#pragma unroll
    for (int mt = 0; mt < 2; mt++)
#pragma unroll
        for (int nt = 0; nt < 4; nt++)
#pragma unroll
            for (int rr = 0; rr < 2; rr++)
                pbias[mt][nt][rr] =
                    *(const float2*)(biasBase + (size_t)(mt * 16 + rr * 8) * Ss + nt * 8 + 2 * t);

    // stage Q (scaled by 0.125*log2e, half2-packed along d)
    const float* Qb = Q + ((size_t)b * Ss + q0) * Dd + h * 64;
#pragma unroll
    for (int l = 0; l < 16; l++) {
        int idx = tid + l * 128;
        int r = idx >> 4;
        int c4 = (idx & 15) << 2;
        float4 v = *(const float4*)(Qb + (size_t)r * Dd + c4);
        Qs[r * QST2 + (c4 >> 1)]     = f2h2(v.x * QPRE, v.y * QPRE);
        Qs[r * QST2 + (c4 >> 1) + 1] = f2h2(v.z * QPRE, v.w * QPRE);
    }

    float o[2][8][4] = {};
    float lr[2][2] = {};
    unsigned* Pw = Ps + (w * 32) * PST2;
    const unsigned* Qw = Qs + (w * 32) * QST2;

    const int NIT = Ss / KTILE;   // 64
    for (int it = 0; it < NIT; it++) {
        // store K (half2 along d) and V (transposed, half2 along k)
#pragma unroll
        for (int l = 0; l < 4; l++) {
            const int r = sr + 8 * l;
            Ks[r * KST2 + skp]     = f2h2(pk[l].x, pk[l].y);
            Ks[r * KST2 + skp + 1] = f2h2(pk[l].z, pk[l].w);
        }
#pragma unroll
        for (int l = 0; l < 2; l++) {
            const int kp = sr + 8 * l;
            Vt[(sc4 + 0) * VST2 + kp] = f2h2(pva[l].x, pvb[l].x);
            Vt[(sc4 + 1) * VST2 + kp] = f2h2(pva[l].y, pvb[l].y);
            Vt[(sc4 + 2) * VST2 + kp] = f2h2(pva[l].z, pvb[l].z);
            Vt[(sc4 + 3) * VST2 + kp] = f2h2(pva[l].w, pvb[l].w);
        }
        __syncthreads();

        // prefetch next K/V tile
        if (it + 1 < NIT) {
            const float* kp_ = KbBase + (size_t)(it + 1) * KTILE * Dd;
            const float* vp_ = VbBase + (size_t)(it + 1) * KTILE * Dd;
#pragma unroll
            for (int l = 0; l < 4; l++)
                pk[l] = *(const float4*)(kp_ + (size_t)(sr + 8 * l) * Dd);
#pragma unroll
            for (int l = 0; l < 2; l++) {
                const int kp = sr + 8 * l;
                pva[l] = *(const float4*)(vp_ + (size_t)(2 * kp) * Dd);
                pvb[l] = *(const float4*)(vp_ + (size_t)(2 * kp + 1) * Dd);
            }
        }

        // S = Q' @ K^T : warp tile 32 x 32, d=64 -> 4 k16 chunks
        float s[2][4][4] = {};
#pragma unroll
        for (int kk = 0; kk < 4; kk++) {
            const int kb = kk * 8;
            unsigned a[2][4];
#pragma unroll
            for (int mt = 0; mt < 2; mt++) {
                const int rb = mt * 16;
                a[mt][0] = Qw[(rb + g) * QST2 + kb + t];
                a[mt][1] = Qw[(rb + g + 8) * QST2 + kb + t];
                a[mt][2] = Qw[(rb + g) * QST2 + kb + t + 4];
                a[mt][3] = Qw[(rb + g + 8) * QST2 + kb + t + 4];
            }
#pragma unroll
            for (int nt = 0; nt < 4; nt++) {
                unsigned bb[2];
                bb[0] = Ks[(nt * 8 + g) * KST2 + kb + t];
                bb[1] = Ks[(nt * 8 + g) * KST2 + kb + t + 4];
                mma16(s[0][nt], a[0], bb);
                mma16(s[1][nt], a[1], bb);
            }
        }

        // exp2(s' + b*log2e), row-sums, pack P to half2
#pragma unroll
        for (int mt = 0; mt < 2; mt++)
#pragma unroll
            for (int nt = 0; nt < 4; nt++) {
                const float2 b0 = pbias[mt][nt][0];
                const float2 b1 = pbias[mt][nt][1];
                float p0 = exp2f(fmaf(b0.x, LOG2E, s[mt][nt][0]));
                float p1 = exp2f(fmaf(b0.y, LOG2E, s[mt][nt][1]));
                float p2 = exp2f(fmaf(b1.x, LOG2E, s[mt][nt][2]));
                float p3 = exp2f(fmaf(b1.y, LOG2E, s[mt][nt][3]));
                lr[mt][0] += p0 + p1;
                lr[mt][1] += p2 + p3;
                Pw[(mt * 16 + g) * PST2 + nt * 4 + t]     = f2h2(p0, p1);
                Pw[(mt * 16 + g + 8) * PST2 + nt * 4 + t] = f2h2(p2, p3);
            }

        // prefetch next bias tile
        if (it + 1 < NIT) {
            const float* bp = biasBase + (it + 1) * KTILE;
#pragma unroll
            for (int mt = 0; mt < 2; mt++)
#pragma unroll
                for (int nt = 0; nt < 4; nt++)
#pragma unroll
                    for (int rr = 0; rr < 2; rr++)
                        pbias[mt][nt][rr] =
                            *(const float2*)(bp + (size_t)(mt * 16 + rr * 8) * Ss + nt * 8 + 2 * t);
        }
        __syncwarp();

        // O += P @ V : warp tile 32 x 64, KTILE=32 -> 2 k16 chunks
#pragma unroll
        for (int kk = 0; kk < 2; kk++) {
            const int kb = kk * 8;
            unsigned a[2][4];
#pragma unroll
            for (int mt = 0; mt < 2; mt++) {
                const int rb = mt * 16;
                a[mt][0] = Pw[(rb + g) * PST2 + kb + t];
                a[mt][1] = Pw[(rb + g + 8) * PST2 + kb + t];
                a[mt][2] = Pw[(rb + g) * PST2 + kb + t + 4];
                a[mt][3] = Pw[(rb + g + 8) * PST2 + kb + t + 4];
            }
#pragma unroll
            for (int nt = 0; nt < 8; nt++) {
                unsigned bb[2];
                bb[0] = Vt[(nt * 8 + g) * VST2 + kb + t];
                bb[1] = Vt[(nt * 8 + g) * VST2 + kb + t + 4];
                mma16(o[0][nt], a[0], bb);
                mma16(o[1][nt], a[1], bb);
            }
        }
        __syncthreads();
    }

#pragma unroll
    for (int mt = 0; mt < 2; mt++)
#pragma unroll
        for (int hf = 0; hf < 2; hf++) {
            float v = lr[mt][hf];
            v += __shfl_xor_sync(0xffffffffu, v, 1);
            v += __shfl_xor_sync(0xffffffffu, v, 2);
            lr[mt][hf] = 1.f / v;
        }

    float* Ob = O + ((size_t)b * Ss + q0 + w * 32) * Dd + h * 64;
#pragma unroll
    for (int mt = 0; mt < 2; mt++)
#pragma unroll
        for (int nt = 0; nt < 8; nt++) {
            const int cg = nt * 8 + 2 * t;
            float2 r0v = {o[mt][nt][0] * lr[mt][0], o[mt][nt][1] * lr[mt][0]};
            float2 r1v = {o[mt][nt][2] * lr[mt][1], o[mt][nt][3] * lr[mt][1]};
            *(float2*)(Ob + (size_t)(mt * 16 + g) * Dd + cg) = r0v;
            *(float2*)(Ob + (size_t)(mt * 16 + g + 8) * Dd + cg) = r1v;
        }
}

// ---------------------------------------------------------------------------
extern "C" void kernel_launch(void* const* d_in, const int* in_sizes, int n_in,
                              void* d_out, int out_size)
{
    (void)in_sizes; (void)n_in;
    const float* queries   = (const float*)d_in[0];
    const float* keys      = (const float*)d_in[1];
    const float* values    = (const float*)d_in[2];
    const float* attn_bias = (const float*)d_in[3];
    const float* Wq = (const float*)d_in[4];
    const float* bq = (const float*)d_in[5];
    const float* Wk = (const float*)d_in[6];
    const float* bk = (const float*)d_in[7];
    const float* Wv = (const float*)d_in[8];
    const float* bv = (const float*)d_in[9];
    const float* Wo = (const float*)d_in[10];
    const float* bo = (const float*)d_in[11];

    float* out = (float*)d_out;

    float *pq, *patt, *pk, *pv;
    cudaGetSymbolAddress((void**)&pq,   g_q);
    cudaGetSymbolAddress((void**)&patt, g_att);
    cudaGetSymbolAddress((void**)&pk,   g_k);
    cudaGetSymbolAddress((void**)&pv,   g_v);

    const bool full_out = (out_size >= 3 * BSD);
    float* kdst = full_out ? out + BSD     : pk;
    float* vdst = full_out ? out + 2 * BSD : pv;

    dim3 qkvgrid(Dd / 128, (Bb * Ss) / 128, 3);  // (8, 32, 3)
    qkv_gemm<<<qkvgrid, 256>>>(queries, keys, values,
                               Wq, Wk, Wv, bq, bk, bv,
                               pq, kdst, vdst, Dd, Dd);

    dim3 agrid(Ss / 128, Bb * Hh);               // (16, 32)
    attn_f16<<<agrid, 128>>>(pq, kdst, vdst, attn_bias, patt);

    dim3 ggrid(Dd / 128, (Bb * Ss) / 128);       // (8, 32)
    gemm_f16<<<ggrid, 256>>>(patt, Wo, bo, out, Dd, Dd);
}

// round 9
// speedup vs baseline: 1.5700x; 1.1111x over previous
#include <cuda_runtime.h>
#include <cuda_fp16.h>
#include <cstdint>

#define Bb 2
#define Ss 2048
#define Dd 1024
#define Hh 16
#define BSD (Bb * Ss * Dd) /* 4194304 */
#define DD (Dd * Dd)

// fp32 scratch (cache fallback)
static __device__ float g_k[BSD];
static __device__ float g_v[BSD];
// half scratch
static __device__ __half g_xq[BSD], g_xk[BSD], g_xv[BSD];   // converted inputs
static __device__ __half g_qh[BSD], g_kh[BSD], g_vh[BSD];   // projected q/k/v
static __device__ __half g_ah[BSD];                          // attention output
static __device__ __half g_wqh[DD], g_wkh[DD], g_wvh[DD], g_woh[DD];

__device__ __forceinline__ unsigned f2h2(float lo, float hi) {
    __half2 h = __floats2half2_rn(lo, hi);
    return *(unsigned*)&h;
}

__device__ __forceinline__ void mma16(float* c, const unsigned* a, const unsigned* b) {
    asm volatile(
        "mma.sync.aligned.m16n8k16.row.col.f32.f16.f16.f32 "
        "{%0,%1,%2,%3}, {%4,%5,%6,%7}, {%8,%9}, {%0,%1,%2,%3};\n"
        : "+f"(c[0]), "+f"(c[1]), "+f"(c[2]), "+f"(c[3])
        : "r"(a[0]), "r"(a[1]), "r"(a[2]), "r"(a[3]), "r"(b[0]), "r"(b[1]));
}

__device__ __forceinline__ uint32_t smem_u32(const void* p) {
    uint32_t a;
    asm("{ .reg .u64 t; cvta.to.shared.u64 t, %1; cvt.u32.u64 %0, t; }"
        : "=r"(a) : "l"(p));
    return a;
}

#define CP_ASYNC16(dst, src) \
    asm volatile("cp.async.cg.shared.global [%0], [%1], 16;" :: "r"(dst), "l"(src))
#define CP_COMMIT() asm volatile("cp.async.commit_group;" ::: "memory")
#define CP_WAIT(n)  asm volatile("cp.async.wait_group %0;" :: "n"(n) : "memory")

#define LDSM_X4_T(r0, r1, r2, r3, addr)                                        \
    asm volatile("ldmatrix.sync.aligned.m8n8.x4.trans.shared.b16 "             \
                 "{%0,%1,%2,%3}, [%4];"                                        \
                 : "=r"(r0), "=r"(r1), "=r"(r2), "=r"(r3) : "r"(addr))

// ===========================================================================
// Pre-convert fp32 -> fp16 (3 inputs + 4 weights), 8 elts/thread
// ===========================================================================
__global__ __launch_bounds__(256, 4)
void cvt7(const float* q, const float* k, const float* v,
          const float* wq, const float* wk, const float* wv, const float* wo,
          __half* qh, __half* kh, __half* vh,
          __half* wqh, __half* wkh, __half* wvh, __half* woh)
{
    const int z = blockIdx.y;
    const float* s; __half* d; int n;
    switch (z) {
        case 0: s = q;  d = qh;  n = BSD; break;
        case 1: s = k;  d = kh;  n = BSD; break;
        case 2: s = v;  d = vh;  n = BSD; break;
        case 3: s = wq; d = wqh; n = DD;  break;
        case 4: s = wk; d = wkh; n = DD;  break;
        case 5: s = wv; d = wvh; n = DD;  break;
        default: s = wo; d = woh; n = DD; break;
    }
    const size_t i = ((size_t)blockIdx.x * 256 + threadIdx.x) * 8;
    if (i >= (size_t)n) return;
    const float4 a = *(const float4*)(s + i);
    const float4 b2 = *(const float4*)(s + i + 4);
    uint4 u = {f2h2(a.x, a.y), f2h2(a.z, a.w), f2h2(b2.x, b2.y), f2h2(b2.z, b2.w)};
    *(uint4*)(d + i) = u;
}

// ===========================================================================
// GEMM (half x half -> fp32): C = A @ W^T + bias. 128x128 tile, BK=32,
// 256 thr / 8 warps, warp tile 32x64, cp.async double-buffer. 2 CTAs/SM.
// ===========================================================================
#define GST2 20
#define GBUFU (128 * GST2)   /* 2560 u32 per operand buffer */

__device__ __forceinline__
void gemm_core(const __half* __restrict__ A, const __half* __restrict__ W,
               const float* __restrict__ bias, float* Cf, __half* Ch,
               int N, int K, int bm, int bn, unsigned* As, unsigned* Bs)
{
    const int tid = threadIdx.x;
    const int w = tid >> 5, lane = tid & 31;
    const int g = lane >> 2, t = lane & 3;
    const int wm = (w & 3) * 32;
    const int wn = (w >> 2) * 64;

    const uint32_t sA = smem_u32(As);
    const uint32_t sB = smem_u32(Bs);

    float c[2][8][4] = {};
    const int NCH = K / 32;

    // prologue: stream chunk 0 into buffer 0 (128 rows x 4 segs of 16B)
#pragma unroll
    for (int l = 0; l < 2; l++) {
        const int idx = tid + l * 256;          // 0..511
        const int row = idx >> 2;               // 0..127
        const int seg = idx & 3;                // 16B segment (32 halfs/row)
        const uint32_t off = (uint32_t)(row * GST2 + seg * 4) * 4;
        CP_ASYNC16(sA + off, A + (size_t)(bm + row) * K + seg * 8);
        CP_ASYNC16(sB + off, W + (size_t)(bn + row) * K + seg * 8);
    }
    CP_COMMIT();

    for (int ch = 0; ch < NCH; ch++) {
        if (ch + 1 < NCH) {
            const uint32_t bo = (uint32_t)(((ch + 1) & 1) * GBUFU) * 4;
            const int k0 = (ch + 1) * 32;
#pragma unroll
            for (int l = 0; l < 2; l++) {
                const int idx = tid + l * 256;
                const int row = idx >> 2;
                const int seg = idx & 3;
                const uint32_t off = (uint32_t)(row * GST2 + seg * 4) * 4;
                CP_ASYNC16(sA + bo + off, A + (size_t)(bm + row) * K + k0 + seg * 8);
                CP_ASYNC16(sB + bo + off, W + (size_t)(bn + row) * K + k0 + seg * 8);
            }
            CP_COMMIT();
            CP_WAIT(1);
        } else {
            CP_WAIT(0);
        }
        __syncthreads();

        const unsigned* Ac = As + (ch & 1) * GBUFU;
        const unsigned* Bc = Bs + (ch & 1) * GBUFU;
#pragma unroll
        for (int kk = 0; kk < 2; kk++) {
            const int kb = kk * 8;
            unsigned a[2][4];
#pragma unroll
            for (int mt = 0; mt < 2; mt++) {
                const int rb = wm + mt * 16;
                a[mt][0] = Ac[(rb + g) * GST2 + kb + t];
                a[mt][1] = Ac[(rb + g + 8) * GST2 + kb + t];
                a[mt][2] = Ac[(rb + g) * GST2 + kb + t + 4];
                a[mt][3] = Ac[(rb + g + 8) * GST2 + kb + t + 4];
            }
#pragma unroll
            for (int nt = 0; nt < 8; nt++) {
                const int nb = wn + nt * 8;
                unsigned b[2];
                b[0] = Bc[(nb + g) * GST2 + kb + t];
                b[1] = Bc[(nb + g) * GST2 + kb + t + 4];
                mma16(c[0][nt], a[0], b);
                mma16(c[1][nt], a[1], b);
            }
        }
        __syncthreads();
    }

#pragma unroll
    for (int mt = 0; mt < 2; mt++) {
        const int r0 = bm + wm + mt * 16 + g;
#pragma unroll
        for (int nt = 0; nt < 8; nt++) {
            const int col = bn + wn + nt * 8 + 2 * t;
            const float2 bv = *(const float2*)(bias + col);
            float2 o0 = {c[mt][nt][0] + bv.x, c[mt][nt][1] + bv.y};
            float2 o1 = {c[mt][nt][2] + bv.x, c[mt][nt][3] + bv.y};
            if (Cf) {
                *(float2*)(Cf + (size_t)r0 * N + col) = o0;
                *(float2*)(Cf + (size_t)(r0 + 8) * N + col) = o1;
            }
            if (Ch) {
                *(unsigned*)(Ch + (size_t)r0 * N + col) = f2h2(o0.x, o0.y);
                *(unsigned*)(Ch + (size_t)(r0 + 8) * N + col) = f2h2(o1.x, o1.y);
            }
        }
    }
}

__global__ __launch_bounds__(256, 2)
void gemm_h(const __half* __restrict__ A, const __half* __restrict__ W,
            const float* __restrict__ bias, float* Cf, __half* Ch, int N, int K)
{
    __shared__ unsigned As[2 * GBUFU];
    __shared__ unsigned Bs[2 * GBUFU];
    gemm_core(A, W, bias, Cf, Ch, N, K, blockIdx.y * 128, blockIdx.x * 128, As, Bs);
}

__global__ __launch_bounds__(256, 2)
void qkv_gemm(const __half* xq, const __half* xk, const __half* xv,
              const __half* wq, const __half* wk, const __half* wv,
              const float* b0, const float* b1, const float* b2,
              __half* qh, float* kf, __half* kh, float* vf, __half* vh,
              int N, int K)
{
    __shared__ unsigned As[2 * GBUFU];
    __shared__ unsigned Bs[2 * GBUFU];
    const int z = blockIdx.z;
    const __half* A = (z == 0) ? xq : (z == 1) ? xk : xv;
    const __half* W = (z == 0) ? wq : (z == 1) ? wk : wv;
    const float* bi = (z == 0) ? b0 : (z == 1) ? b1 : b2;
    float* Cf = (z == 0) ? nullptr : (z == 1) ? kf : vf;
    __half* Ch = (z == 0) ? qh : (z == 1) ? kh : vh;
    gemm_core(A, W, bi, Cf, Ch, N, K, blockIdx.y * 128, blockIdx.x * 128, As, Bs);
}

// ===========================================================================
// Attention (all-half): 128 thr (4 warps x 32 q-rows), 2 CTAs/SM.
// k-tiles of 32, cp.async double-buffered K/V, ldmatrix.trans for V.
// Attention rows are 64 halfs = 8 x 16B segments (staging covers ALL 8).
// exp(s/8 + b) = exp2(s*QPRE + b*LOG2E). No max-subtraction.
// ===========================================================================
#define KTILE 32
#define QSTH 36
#define KSTH 36
#define VSTH 36
#define PSTH 20
#define KBUFU (KTILE * KSTH)   /* 1152 */
#define VBUFU (KTILE * VSTH)   /* 1152 */
#define AO_K 4608              /* after Qs 128*36 */
#define AO_V (AO_K + 2 * KBUFU)  /* 6912 */
#define AO_P (AO_V + 2 * VBUFU)  /* 9216 */
#define ATTN_UINTS (AO_P + 128 * PSTH)  /* 11776 = 47104 B */
#define QPRE 0.18033688011112042f       /* 0.125 * log2(e) */
#define LOG2E 1.4426950408889634f

__global__ __launch_bounds__(128, 2)
void attn_h(const __half* __restrict__ Q, const __half* __restrict__ Kh,
            const __half* __restrict__ Vh, const float* __restrict__ bias,
            __half* __restrict__ O)
{
    __shared__ unsigned sm[ATTN_UINTS];
    unsigned* Qs = sm;
    unsigned* Ks = sm + AO_K;
    unsigned* Vt = sm + AO_V;
    unsigned* Ps = sm + AO_P;

    const int tid = threadIdx.x;
    const int w = tid >> 5, lane = tid & 31;
    const int g = lane >> 2, t = lane & 3;
    const int q0 = blockIdx.x * 128;
    const int bh = blockIdx.y;
    const int b = bh >> 4, h = bh & 15;

    const uint32_t sQ = smem_u32(Qs);
    const uint32_t sK = smem_u32(Ks);
    const uint32_t sV = smem_u32(Vt);

    // row = srow + 16*l, seg covers the FULL 8 segments (64 halfs) per row
    const int srow = tid >> 3;        // 0..15
    const int sseg = tid & 7;         // 0..7
    const __half* KbBase = Kh + (size_t)b * Ss * Dd + h * 64 + sseg * 8;
    const __half* VbBase = Vh + (size_t)b * Ss * Dd + h * 64 + sseg * 8;
    const float* biasBase = bias + (size_t)b * Ss * Ss + (size_t)(q0 + w * 32 + g) * Ss;

    // prologue: KV tile 0 (32 rows x 8 segs) + Q (128 rows x 8 segs)
    {
#pragma unroll
        for (int l = 0; l < 2; l++) {
            const int row = srow + 16 * l;
            const uint32_t off = (uint32_t)(row * KSTH + sseg * 4) * 4;
            CP_ASYNC16(sK + off, KbBase + (size_t)row * Dd);
            CP_ASYNC16(sV + off, VbBase + (size_t)row * Dd);
        }
        const __half* Qb = Q + ((size_t)b * Ss + q0) * Dd + h * 64 + sseg * 8;
#pragma unroll
        for (int l = 0; l < 8; l++) {
            const int row = srow + 16 * l;   // 0..127
            CP_ASYNC16(sQ + (uint32_t)(row * QSTH + sseg * 4) * 4,
                       Qb + (size_t)row * Dd);
        }
    }
    CP_COMMIT();

    // bias tile 0 prefetch (pre-multiplied by LOG2E)
    float2 pbias[2][4][2];
#pragma unroll
    for (int mt = 0; mt < 2; mt++)
#pragma unroll
        for (int nt = 0; nt < 4; nt++)
#pragma unroll
            for (int rr = 0; rr < 2; rr++) {
                float2 v = *(const float2*)(biasBase + (size_t)(mt * 16 + rr * 8) * Ss + nt * 8 + 2 * t);
                pbias[mt][nt][rr] = {v.x * LOG2E, v.y * LOG2E};
            }

    float o[2][8][4] = {};
    float lr[2][2] = {};
    unsigned* Pw = Ps + (w * 32) * PSTH;
    const unsigned* Qw = Qs + (w * 32) * QSTH;

    const int NIT = Ss / KTILE;   // 64
    for (int it = 0; it < NIT; it++) {
        if (it + 1 < NIT) {
            const uint32_t kbo = (uint32_t)(((it + 1) & 1) * KBUFU) * 4;
            const uint32_t vbo = (uint32_t)(((it + 1) & 1) * VBUFU) * 4;
#pragma unroll
            for (int l = 0; l < 2; l++) {
                const int row = srow + 16 * l;
                const size_t roff = (size_t)((it + 1) * KTILE + row) * Dd;
                const uint32_t off = (uint32_t)(row * KSTH + sseg * 4) * 4;
                CP_ASYNC16(sK + kbo + off, KbBase + roff);
                CP_ASYNC16(sV + vbo + off, VbBase + roff);
            }
            CP_COMMIT();
            CP_WAIT(1);
        } else {
            CP_WAIT(0);
        }
        __syncthreads();

        const unsigned* Kc = Ks + (it & 1) * KBUFU;
        const uint32_t vb = sV + (uint32_t)((it & 1) * VBUFU) * 4;

        // S = Q @ K^T : warp tile 32 x 32, d=64 -> 4 k16 chunks
        float s[2][4][4] = {};
#pragma unroll
        for (int kk = 0; kk < 4; kk++) {
            const int kb = kk * 8;
            unsigned a[2][4];
#pragma unroll
            for (int mt = 0; mt < 2; mt++) {
                const int rb = mt * 16;
                a[mt][0] = Qw[(rb + g) * QSTH + kb + t];
                a[mt][1] = Qw[(rb + g + 8) * QSTH + kb + t];
                a[mt][2] = Qw[(rb + g) * QSTH + kb + t + 4];
                a[mt][3] = Qw[(rb + g + 8) * QSTH + kb + t + 4];
            }
#pragma unroll
            for (int nt = 0; nt < 4; nt++) {
                unsigned bb[2];
                bb[0] = Kc[(nt * 8 + g) * KSTH + kb + t];
                bb[1] = Kc[(nt * 8 + g) * KSTH + kb + t + 4];
                mma16(s[0][nt], a[0], bb);
                mma16(s[1][nt], a[1], bb);
            }
        }

        // p = exp2(s*QPRE + b*log2e), row-sums, pack P
#pragma unroll
        for (int mt = 0; mt < 2; mt++)
#pragma unroll
            for (int nt = 0; nt < 4; nt++) {
                const float2 b0 = pbias[mt][nt][0];
                const float2 b1 = pbias[mt][nt][1];
                float p0 = exp2f(fmaf(s[mt][nt][0], QPRE, b0.x));
                float p1 = exp2f(fmaf(s[mt][nt][1], QPRE, b0.y));
                float p2 = exp2f(fmaf(s[mt][nt][2], QPRE, b1.x));
                float p3 = exp2f(fmaf(s[mt][nt][3], QPRE, b1.y));
                lr[mt][0] += p0 + p1;
                lr[mt][1] += p2 + p3;
                Pw[(mt * 16 + g) * PSTH + nt * 4 + t]     = f2h2(p0, p1);
                Pw[(mt * 16 + g + 8) * PSTH + nt * 4 + t] = f2h2(p2, p3);
            }

        // prefetch next bias tile
        if (it + 1 < NIT) {
            const float* bp = biasBase + (it + 1) * KTILE;
#pragma unroll
            for (int mt = 0; mt < 2; mt++)
#pragma unroll
                for (int nt = 0; nt < 4; nt++)
#pragma unroll
                    for (int rr = 0; rr < 2; rr++) {
                        float2 v = *(const float2*)(bp + (size_t)(mt * 16 + rr * 8) * Ss + nt * 8 + 2 * t);
                        pbias[mt][nt][rr] = {v.x * LOG2E, v.y * LOG2E};
                    }
        }
        __syncwarp();

        // O += P @ V : warp tile 32 x 64; V fragments via ldmatrix.x4.trans
#pragma unroll
        for (int kk = 0; kk < 2; kk++) {
            const int kb = kk * 8;
            unsigned a[2][4];
#pragma unroll
            for (int mt = 0; mt < 2; mt++) {
                const int rb = mt * 16;
                a[mt][0] = Pw[(rb + g) * PSTH + kb + t];
                a[mt][1] = Pw[(rb + g + 8) * PSTH + kb + t];
                a[mt][2] = Pw[(rb + g) * PSTH + kb + t + 4];
                a[mt][3] = Pw[(rb + g + 8) * PSTH + kb + t + 4];
            }
            const int m = lane >> 3, rr = lane & 7;
#pragma unroll
            for (int ntp = 0; ntp < 4; ntp++) {
                const uint32_t vaddr = vb +
                    (uint32_t)((kk * 16 + (m & 1) * 8 + rr) * VSTH +
                               (2 * ntp + (m >> 1)) * 4) * 4;
                unsigned bv[4];
                LDSM_X4_T(bv[0], bv[1], bv[2], bv[3], vaddr);
                mma16(o[0][2 * ntp],     a[0], &bv[0]);
                mma16(o[1][2 * ntp],     a[1], &bv[0]);
                mma16(o[0][2 * ntp + 1], a[0], &bv[2]);
                mma16(o[1][2 * ntp + 1], a[1], &bv[2]);
            }
        }
        __syncthreads();
    }

#pragma unroll
    for (int mt = 0; mt < 2; mt++)
#pragma unroll
        for (int hf = 0; hf < 2; hf++) {
            float v = lr[mt][hf];
            v += __shfl_xor_sync(0xffffffffu, v, 1);
            v += __shfl_xor_sync(0xffffffffu, v, 2);
            lr[mt][hf] = 1.f / v;
        }

    __half* Ob = O + ((size_t)b * Ss + q0 + w * 32) * Dd + h * 64;
#pragma unroll
    for (int mt = 0; mt < 2; mt++)
#pragma unroll
        for (int nt = 0; nt < 8; nt++) {
            const int cg = nt * 8 + 2 * t;
            *(unsigned*)(Ob + (size_t)(mt * 16 + g) * Dd + cg) =
                f2h2(o[mt][nt][0] * lr[mt][0], o[mt][nt][1] * lr[mt][0]);
            *(unsigned*)(Ob + (size_t)(mt * 16 + g + 8) * Dd + cg) =
                f2h2(o[mt][nt][2] * lr[mt][1], o[mt][nt][3] * lr[mt][1]);
        }
}

// ---------------------------------------------------------------------------
extern "C" void kernel_launch(void* const* d_in, const int* in_sizes, int n_in,
                              void* d_out, int out_size)
{
    (void)in_sizes; (void)n_in;
    const float* queries   = (const float*)d_in[0];
    const float* keys      = (const float*)d_in[1];
    const float* values    = (const float*)d_in[2];
    const float* attn_bias = (const float*)d_in[3];
    const float* Wq = (const float*)d_in[4];
    const float* bq = (const float*)d_in[5];
    const float* Wk = (const float*)d_in[6];
    const float* bk = (const float*)d_in[7];
    const float* Wv = (const float*)d_in[8];
    const float* bv = (const float*)d_in[9];
    const float* Wo = (const float*)d_in[10];
    const float* bo = (const float*)d_in[11];

    float* out = (float*)d_out;

    float *pkf, *pvf;
    cudaGetSymbolAddress((void**)&pkf, g_k);
    cudaGetSymbolAddress((void**)&pvf, g_v);
    __half *xq, *xk, *xv, *qh, *kh, *vh, *ah, *wqh, *wkh, *wvh, *woh;
    cudaGetSymbolAddress((void**)&xq,  g_xq);
    cudaGetSymbolAddress((void**)&xk,  g_xk);
    cudaGetSymbolAddress((void**)&xv,  g_xv);
    cudaGetSymbolAddress((void**)&qh,  g_qh);
    cudaGetSymbolAddress((void**)&kh,  g_kh);
    cudaGetSymbolAddress((void**)&vh,  g_vh);
    cudaGetSymbolAddress((void**)&ah,  g_ah);
    cudaGetSymbolAddress((void**)&wqh, g_wqh);
    cudaGetSymbolAddress((void**)&wkh, g_wkh);
    cudaGetSymbolAddress((void**)&wvh, g_wvh);
    cudaGetSymbolAddress((void**)&woh, g_woh);

    const bool full_out = (out_size >= 3 * BSD);
    float* kdst = full_out ? out + BSD     : pkf;
    float* vdst = full_out ? out + 2 * BSD : pvf;

    // 1) fp32 -> fp16 conversion pass
    dim3 cgrid(BSD / (256 * 8), 7);              // (2048, 7)
    cvt7<<<cgrid, 256>>>(queries, keys, values, Wq, Wk, Wv, Wo,
                         xq, xk, xv, wqh, wkh, wvh, woh);

    // 2) QKV projections (half), k/v also in fp32 for the cache outputs
    dim3 qkvgrid(Dd / 128, (Bb * Ss) / 128, 3);  // (8, 32, 3)
    qkv_gemm<<<qkvgrid, 256>>>(xq, xk, xv, wqh, wkh, wvh, bq, bk, bv,
                               qh, kdst, kh, vdst, vh, Dd, Dd);

    // 3) attention (all-half)
    dim3 agrid(Ss / 128, Bb * Hh);               // (16, 32)
    attn_h<<<agrid, 128>>>(qh, kh, vh, attn_bias, ah);

    // 4) output projection
    dim3 ggrid(Dd / 128, (Bb * Ss) / 128);       // (8, 32)
    gemm_h<<<ggrid, 256>>>(ah, woh, bo, out, nullptr, Dd, Dd);
}